// round 16
// baseline (speedup 1.0000x reference)
#include <cuda_runtime.h>
#include <math.h>

#define BB 4
#define CC 32
#define SS 64
#define MM 8
#define NT 262144   // 64^3
#define NCH 128     // B*C
#define SPAD 65
#define TWOPI_64 0.0981747704246810387f

// Scratch (device globals)
__device__ float g_part[NCH * 32 * 3];    // per (bc,pair): s0,c0,c2
__device__ float g_AB[NCH * 64 * 128];    // per (bc,n1): A[64],B[64]  (4 MB)
__device__ float g_x1[NCH * 512];
__device__ float g_yp[4*NCH*512];         // partial y, four i-groups
__device__ float g_wp[CC*CC*512];
__device__ float g_wm[CC*CC*512];

__device__ __forceinline__ void init_tables(float* s_ct, float* s_st, int t) {
    if (t < 64) {
        float sv, cv;
        sincosf((float)t * TWOPI_64, &sv, &cv);
        s_ct[t] = cv;
        s_st[t] = sv;
    }
}

// ---------------- forward stage A: plane-pair blocks (+ weight prep blocks) ----
// grid (33, 128): blockIdx.x < 32 -> transform; blockIdx.x == 32 -> weight prep
__global__ void __launch_bounds__(256) k_fwdA(const float* __restrict__ x,
                                              const float* __restrict__ w) {
    __shared__ float s_ct[64], s_st[64];
    __shared__ float sx[2][64*SPAD];
    __shared__ float sP[2][8][SPAD], sQ[2][8][SPAD];
    __shared__ float s_red[3][8];
    int t  = threadIdx.x;

    if (blockIdx.x == 32) {
        // weight prep: 128 blocks x 256 threads x 16 elements
        int chunk = blockIdx.y;
        #pragma unroll
        for (int r = 0; r < 16; r++) {
            int idx = chunk * 4096 + r * 256 + t;
            int k  = idx & 511;
            int io = idx >> 9;
            int k1 = k >> 6, k2 = (k >> 3) & 7, k3 = k & 7;
            int nk = (((8-k1)&7) << 6) | (((8-k2)&7) << 3) | ((8-k3)&7);
            float a = w[(io<<9) + k];
            float b = w[(io<<9) + nk];
            g_wp[idx] = 0.5f * (a + b);
            g_wm[idx] = 0.5f * (a - b);
        }
        return;
    }

    int pr = blockIdx.x;      // 0..31
    int bc = blockIdx.y;      // 0..127
    int n1a = pr;
    int n1b = (pr == 0) ? 32 : 64 - pr;
    init_tables(s_ct, s_st, t);

    const float* xa = x + ((size_t)bc << 18) + (n1a << 12);
    const float* xb = x + ((size_t)bc << 18) + (n1b << 12);
    #pragma unroll
    for (int r = 0; r < 4; r++) {
        int idx = (t << 2) + (r << 10);
        int row = idx >> 6, col = idx & 63;
        float4 va = *(const float4*)(xa + idx);
        float4 vb = *(const float4*)(xb + idx);
        float* da = &sx[0][row*SPAD + col];
        float* db = &sx[1][row*SPAD + col];
        da[0]=va.x; da[1]=va.y; da[2]=va.z; da[3]=va.w;
        db[0]=vb.x; db[1]=vb.y; db[2]=vb.z; db[3]=vb.w;
    }
    __syncthreads();

    // correlations
    float s0 = 0.f, c0 = 0.f, c2 = 0.f;
    {
        int ppA = (pr == 0) ? 0 : 1;
        int ppB = (pr == 0) ? 1 : 0;
        int base = t << 4;
        int n2  = base >> 6;
        int n30 = base & 63;
        int r2  = (64 - n2) & 63;
        #pragma unroll
        for (int e = 0; e < 16; e++) {
            int n3  = n30 + e;
            int r3  = (64 - n3) & 63;
            int r3b = (62 - n3) & 63;
            float va = sx[0][n2*SPAD + n3];
            float ua = sx[ppA][r2*SPAD + r3];
            float za = sx[ppA][r2*SPAD + r3b];
            s0 = fmaf(va, va, s0); c0 = fmaf(va, ua, c0); c2 = fmaf(va, za, c2);
            float vb = sx[1][n2*SPAD + n3];
            float ub = sx[ppB][r2*SPAD + r3];
            float zb = sx[ppB][r2*SPAD + r3b];
            s0 = fmaf(vb, vb, s0); c0 = fmaf(vb, ub, c0); c2 = fmaf(vb, zb, c2);
        }
    }

    // step 2: per (plane,n2) row: Cc/Cs (n3 pair symmetry + Chebyshev), then P,Q
    if (t < 128) {
        int p = t >> 6, n2 = t & 63;
        const float* row = &sx[p][n2*SPAD];
        float Cc[8], Cs[7];
        float v0 = row[0], v32 = row[32];
        #pragma unroll
        for (int k = 0; k < 8; k++) Cc[k] = v0 + ((k & 1) ? -v32 : v32);
        #pragma unroll
        for (int k = 0; k < 7; k++) Cs[k] = 0.f;
        for (int n3 = 1; n3 < 32; n3++) {
            float vA = row[n3], vB = row[64 - n3];
            float sp = vA + vB, sm = vA - vB;
            float c1 = s_ct[n3], s1 = s_st[n3];
            float tw = c1 + c1;
            float tc[7], ts[7];
            tc[0] = c1; ts[0] = s1;
            tc[1] = fmaf(tw, c1, -1.f);
            ts[1] = tw * s1;
            #pragma unroll
            for (int k = 2; k < 7; k++) {
                tc[k] = fmaf(tw, tc[k-1], -tc[k-2]);
                ts[k] = fmaf(tw, ts[k-1], -ts[k-2]);
            }
            Cc[0] += sp;
            #pragma unroll
            for (int k = 1; k < 8; k++) {
                Cc[k]   = fmaf(sp, tc[k-1], Cc[k]);
                Cs[k-1] = fmaf(sm, ts[k-1], Cs[k-1]);
            }
        }
        #pragma unroll
        for (int k = 0; k < 8; k++) {
            float cs_ = (k == 0) ? 0.f : Cs[k-1];
            float ck = s_ct[k], sk = s_st[k];
            sP[p][k][n2] = Cc[k] * (1.f - sk) - cs_ * ck;
            sQ[p][k][n2] = Cc[k] * ck - cs_ * (1.f + sk);
        }
    }
    __syncthreads();

    // step 3: per (plane,k2,k3): A = sum c2*P + s2*Q ; B = sum c2*Q - s2*P
    if (t < 128) {
        int pp = t >> 6, k2 = (t >> 3) & 7, k3 = t & 7;
        float A  = sP[pp][k3][0];
        float Bv = sQ[pp][k3][0];
        float sg = (k2 & 1) ? -1.f : 1.f;
        A  = fmaf(sg, sP[pp][k3][32], A);
        Bv = fmaf(sg, sQ[pp][k3][32], Bv);
        #pragma unroll 4
        for (int n2i = 1; n2i < 32; n2i++) {
            int tt = (k2 * n2i) & 63;
            float c = s_ct[tt], s = s_st[tt];
            float Pa = sP[pp][k3][n2i], Pb = sP[pp][k3][64 - n2i];
            float Qa = sQ[pp][k3][n2i], Qb = sQ[pp][k3][64 - n2i];
            A  = fmaf(c, Pa + Pb, fmaf(s, Qa - Qb, A));
            Bv = fmaf(c, Qa + Qb, fmaf(-s, Pa - Pb, Bv));
        }
        int n1 = pp ? n1b : n1a;
        int ob = (((bc << 6) + n1) << 7);
        g_AB[ob + (k2 << 3) + k3]      = A;
        g_AB[ob + 64 + (k2 << 3) + k3] = Bv;
    }

    // reduce s0,c0,c2 over the block
    unsigned m = 0xffffffffu;
    #pragma unroll
    for (int s = 16; s > 0; s >>= 1) {
        s0 += __shfl_down_sync(m, s0, s);
        c0 += __shfl_down_sync(m, c0, s);
        c2 += __shfl_down_sync(m, c2, s);
    }
    int lane = t & 31, wid = t >> 5;
    if (lane == 0) { s_red[0][wid] = s0; s_red[1][wid] = c0; s_red[2][wid] = c2; }
    __syncthreads();
    if (t == 0) {
        float a0 = 0, a1 = 0, a2 = 0;
        #pragma unroll
        for (int w8 = 0; w8 < 8; w8++) { a0 += s_red[0][w8]; a1 += s_red[1][w8]; a2 += s_red[2][w8]; }
        int base = (bc * 32 + pr) * 3;
        g_part[base + 0] = a0;
        g_part[base + 1] = a1;
        g_part[base + 2] = a2;
    }
}

// ---------------- forward stage B: contract n1, finalize norm1, write x1 ----
__global__ void __launch_bounds__(512) k_fwdB() {
    __shared__ float s_ct[64], s_st[64];
    __shared__ float sAB[64*128];
    __shared__ float s_inv;
    int t  = threadIdx.x;
    int bc = blockIdx.x;
    init_tables(s_ct, s_st, t);
    if (t == 64) {
        float s0 = 0, c0 = 0, c2 = 0;
        #pragma unroll 8
        for (int pr = 0; pr < 32; pr++) {
            int base = (bc * 32 + pr) * 3;
            s0 += g_part[base + 0];
            c0 += g_part[base + 1];
            c2 += g_part[base + 2];
        }
        float v = (float)NT * (s0 + 0.5f * (c0 - c2));
        s_inv = (v > 0.f) ? rsqrtf(v) : 0.f;
    }
    {
        const float4* src = (const float4*)(g_AB + ((size_t)bc << 13));
        float4* dst = (float4*)sAB;
        #pragma unroll
        for (int r = 0; r < 4; r++) dst[t + (r << 9)] = src[t + (r << 9)];
    }
    __syncthreads();

    int k1 = t >> 6, kk = t & 63;
    float H = sAB[kk];                               // n1 = 0
    float sg = (k1 & 1) ? -1.f : 1.f;
    H = fmaf(sg, sAB[(32 << 7) + kk], H);            // n1 = 32
    #pragma unroll 4
    for (int n1 = 1; n1 < 32; n1++) {
        int tt = (k1 * n1) & 63;
        float c = s_ct[tt], s = s_st[tt];
        float Aa = sAB[(n1 << 7) + kk],      Ab = sAB[((64 - n1) << 7) + kk];
        float Ba = sAB[(n1 << 7) + 64 + kk], Bb = sAB[((64 - n1) << 7) + 64 + kk];
        H = fmaf(c, Aa + Ab, fmaf(s, Ba - Bb, H));
    }
    g_x1[bc * 512 + t] = H * s_inv;
}

// ---------------- conv partial: grid (4 ig, 128 bo), 128 thr, float4 ----------
__global__ void __launch_bounds__(128) k_convp() {
    int ig = blockIdx.x;            // 0..3 (i-group of 8)
    int bo = blockIdx.y;            // 0..127
    int b = bo >> 5, o = bo & 31;
    int t = threadIdx.x;
    int k4 = t << 2;                // base k of this thread's float4
    int k1 = k4 >> 6, k2 = (k4 >> 3) & 7, k3b = k4 & 7;   // k3b in {0,4}
    int nkb = (((8-k1)&7) << 6) | (((8-k2)&7) << 3);
    int nk0 = nkb | ((8 - (k3b + 0)) & 7);
    int nk1 = nkb | ((8 - (k3b + 1)) & 7);
    int nk2 = nkb | ((8 - (k3b + 2)) & 7);
    int nk3 = nkb | ((8 - (k3b + 3)) & 7);
    float4 acc = make_float4(0.f, 0.f, 0.f, 0.f);
    #pragma unroll
    for (int ii = 0; ii < 8; ii++) {
        int i = (ig << 3) + ii;
        const float* xA = g_x1 + ((b * 32 + i) << 9);
        int wb = (i * 32 + o) << 9;
        float4 xa  = *(const float4*)(xA + k4);
        float  xr0 = xA[nk0], xr1 = xA[nk1], xr2 = xA[nk2], xr3 = xA[nk3];
        float4 wp4 = *(const float4*)(g_wp + wb + k4);
        float4 wm4 = *(const float4*)(g_wm + wb + k4);
        acc.x = fmaf(xa.x, wp4.x, fmaf(xr0, wm4.x, acc.x));
        acc.y = fmaf(xa.y, wp4.y, fmaf(xr1, wm4.y, acc.y));
        acc.z = fmaf(xa.z, wp4.z, fmaf(xr2, wm4.z, acc.z));
        acc.w = fmaf(xa.w, wp4.w, fmaf(xr3, wm4.w, acc.w));
    }
    *(float4*)(g_yp + (((ig << 7) | bo) << 9) + k4) = acc;
}

// ---------------- I1+I2+I3 fused (+ y assembly + norm2): 512 thr, 2 blk/bo ----
__global__ void __launch_bounds__(512) k_i23(float* __restrict__ out) {
    __shared__ float s_ct[64], s_st[64];
    __shared__ float s_y[512];
    __shared__ float s_tc[4096], s_ts[4096];
    __shared__ float sa[512];
    __shared__ float s_sc;
    int t = threadIdx.x;
    int tile = blockIdx.x;   // 0..1
    int bo   = blockIdx.y;   // 0..127

    init_tables(s_ct, s_st, t);

    float y0 = 0.f;
    #pragma unroll
    for (int ig = 0; ig < 4; ig++) {
        const float* yp = g_yp + (((ig << 7) | bo) << 9);
        y0 += yp[t];
    }
    sa[t] = ((t == 0) ? 1.5f : 1.0f) * y0 * y0;
    __syncthreads();
    for (int s = 256; s > 0; s >>= 1) {
        if (t < s) sa[t] += sa[t + s];
        __syncthreads();
    }
    if (t == 0) {
        float v = sa[0];
        s_sc = (v > 0.f) ? rsqrtf((float)NT * v) / (float)NT : 0.f;
    }
    __syncthreads();
    s_y[t] = y0 * s_sc;
    __syncthreads();

    int j3 = t & 63;
    int jg = t >> 6;   // 0..7

    // stage I1
    {
        float U[8], V[8];
        #pragma unroll
        for (int k3 = 0; k3 < 8; k3++) {
            int t0 = (j3 * k3) & 63;
            int t1 = (j3 * (k3 + 1)) & 63;
            U[k3] = s_ct[t0] - s_st[t1];
            V[k3] = s_ct[t1] - s_st[t0];
        }
        #pragma unroll
        for (int r = 0; r < 8; r++) {
            int kk = jg + 8 * r;
            float a = 0.f, bsum = 0.f;
            #pragma unroll
            for (int k3 = 0; k3 < 8; k3++) {
                float yv = s_y[(kk << 3) + k3];
                a    = fmaf(yv, U[k3], a);
                bsum = fmaf(yv, V[k3], bsum);
            }
            s_tc[(kk << 6) + j3] = a;
            s_ts[(kk << 6) + j3] = bsum;
        }
    }
    __syncthreads();

    float* ob = out + ((size_t)bo << 18);

    // stage I2 for all 4 j2 values; LDS hoisted out of the v loop
    float p[4][8], q[4][8];
    int j2v[4];
    #pragma unroll
    for (int v = 0; v < 4; v++) {
        j2v[v] = tile * 32 + jg * 4 + v;
        #pragma unroll
        for (int k1 = 0; k1 < 8; k1++) { p[v][k1] = 0.f; q[v][k1] = 0.f; }
    }
    #pragma unroll
    for (int k2 = 0; k2 < 8; k2++) {
        float cv[4], sv[4];
        #pragma unroll
        for (int v = 0; v < 4; v++) {
            int tt = (j2v[v] * k2) & 63;
            cv[v] = s_ct[tt];
            sv[v] = s_st[tt];
        }
        #pragma unroll
        for (int k1 = 0; k1 < 8; k1++) {
            float a  = s_tc[((k1 * 8 + k2) << 6) + j3];
            float bb = s_ts[((k1 * 8 + k2) << 6) + j3];
            #pragma unroll
            for (int v = 0; v < 4; v++) {
                p[v][k1] = fmaf(a, cv[v], fmaf(bb,  sv[v], p[v][k1]));
                q[v][k1] = fmaf(bb, cv[v], fmaf(-a, sv[v], q[v][k1]));
            }
        }
    }

    // stage I3: j1 outer (trig hoisted), 4-fold symmetry over j1
    #pragma unroll 1
    for (int j1 = 0; j1 <= 16; j1++) {
        float tcv[7], tsv[7];
        #pragma unroll
        for (int k = 1; k < 8; k++) {
            int tt = (j1 * k) & 63;
            tcv[k-1] = s_ct[tt];
            tsv[k-1] = s_st[tt];
        }
        int o0 = j1 << 12;
        int o1 = ((64 - j1) & 63) << 12;
        int o2 = ((j1 + 32) & 63) << 12;
        int o3 = ((32 - j1) & 63) << 12;
        #pragma unroll
        for (int v = 0; v < 4; v++) {
            float pce = p[v][0], pco = 0.f, qse = 0.f, qso = 0.f;
            #pragma unroll
            for (int k = 1; k < 8; k++) {
                if (k & 1) { pco = fmaf(p[v][k], tcv[k-1], pco); qso = fmaf(q[v][k], tsv[k-1], qso); }
                else       { pce = fmaf(p[v][k], tcv[k-1], pce); qse = fmaf(q[v][k], tsv[k-1], qse); }
            }
            float A = pce + pco, Bv = qse + qso;
            float C = pce - pco, D  = qse - qso;
            float* op = ob + (j2v[v] << 6) + j3;
            op[o0] = A + Bv;
            op[o1] = A - Bv;
            op[o2] = C + D;
            op[o3] = C - D;
        }
    }
}

extern "C" void kernel_launch(void* const* d_in, const int* in_sizes, int n_in,
                              void* d_out, int out_size) {
    const float* x = (const float*)d_in[0];       // (4,32,64,64,64)
    const float* w = (const float*)d_in[1];       // (32,32,8,8,8)
    float* out = (float*)d_out;                   // (4,32,64,64,64)

    k_fwdA<<<dim3(33, NCH), 256>>>(x, w);
    k_fwdB<<<NCH, 512>>>();
    k_convp<<<dim3(4, NCH), 128>>>();
    k_i23<<<dim3(2, NCH), 512>>>(out);
}

// round 17
// speedup vs baseline: 1.0802x; 1.0802x over previous
#include <cuda_runtime.h>
#include <math.h>

#define BB 4
#define CC 32
#define SS 64
#define MM 8
#define NT 262144   // 64^3
#define NCH 128     // B*C
#define SPAD 65
#define TWOPI_64 0.0981747704246810387f

// Scratch (device globals)
__device__ float g_part[NCH * 32 * 3];    // per (bc,pair): s0,c0,c2
__device__ float g_AB[NCH * 64 * 128];    // per (bc,n1): A[64],B[64]  (4 MB)
__device__ float g_x1[NCH * 512];
__device__ float g_yp[4*NCH*512];         // partial y, four i-groups
__device__ float g_wp[CC*CC*512];
__device__ float g_wm[CC*CC*512];

__device__ __forceinline__ void init_tables(float* s_ct, float* s_st, int t) {
    if (t < 64) {
        float sv, cv;
        sincosf((float)t * TWOPI_64, &sv, &cv);
        s_ct[t] = cv;
        s_st[t] = sv;
    }
}

// ---------------- forward stage A: plane-pair blocks (+ weight prep blocks) ----
// grid (33, 128): blockIdx.x < 32 -> transform; blockIdx.x == 32 -> weight prep
__global__ void __launch_bounds__(256) k_fwdA(const float* __restrict__ x,
                                              const float* __restrict__ w) {
    __shared__ float s_ct[64], s_st[64];
    __shared__ float sx[2][64*SPAD];
    __shared__ float sP[2][8][SPAD], sQ[2][8][SPAD];
    __shared__ float s_red[3][8];
    int t  = threadIdx.x;

    if (blockIdx.x == 32) {
        int chunk = blockIdx.y;
        #pragma unroll
        for (int r = 0; r < 16; r++) {
            int idx = chunk * 4096 + r * 256 + t;
            int k  = idx & 511;
            int io = idx >> 9;
            int k1 = k >> 6, k2 = (k >> 3) & 7, k3 = k & 7;
            int nk = (((8-k1)&7) << 6) | (((8-k2)&7) << 3) | ((8-k3)&7);
            float a = w[(io<<9) + k];
            float b = w[(io<<9) + nk];
            g_wp[idx] = 0.5f * (a + b);
            g_wm[idx] = 0.5f * (a - b);
        }
        return;
    }

    int pr = blockIdx.x;      // 0..31
    int bc = blockIdx.y;      // 0..127
    int n1a = pr;
    int n1b = (pr == 0) ? 32 : 64 - pr;
    init_tables(s_ct, s_st, t);

    const float* xa = x + ((size_t)bc << 18) + (n1a << 12);
    const float* xb = x + ((size_t)bc << 18) + (n1b << 12);
    #pragma unroll
    for (int r = 0; r < 4; r++) {
        int idx = (t << 2) + (r << 10);
        int row = idx >> 6, col = idx & 63;
        float4 va = *(const float4*)(xa + idx);
        float4 vb = *(const float4*)(xb + idx);
        float* da = &sx[0][row*SPAD + col];
        float* db = &sx[1][row*SPAD + col];
        da[0]=va.x; da[1]=va.y; da[2]=va.z; da[3]=va.w;
        db[0]=vb.x; db[1]=vb.y; db[2]=vb.z; db[3]=vb.w;
    }
    __syncthreads();

    // correlations
    float s0 = 0.f, c0 = 0.f, c2 = 0.f;
    {
        int ppA = (pr == 0) ? 0 : 1;
        int ppB = (pr == 0) ? 1 : 0;
        int base = t << 4;
        int n2  = base >> 6;
        int n30 = base & 63;
        int r2  = (64 - n2) & 63;
        #pragma unroll
        for (int e = 0; e < 16; e++) {
            int n3  = n30 + e;
            int r3  = (64 - n3) & 63;
            int r3b = (62 - n3) & 63;
            float va = sx[0][n2*SPAD + n3];
            float ua = sx[ppA][r2*SPAD + r3];
            float za = sx[ppA][r2*SPAD + r3b];
            s0 = fmaf(va, va, s0); c0 = fmaf(va, ua, c0); c2 = fmaf(va, za, c2);
            float vb = sx[1][n2*SPAD + n3];
            float ub = sx[ppB][r2*SPAD + r3];
            float zb = sx[ppB][r2*SPAD + r3b];
            s0 = fmaf(vb, vb, s0); c0 = fmaf(vb, ub, c0); c2 = fmaf(vb, zb, c2);
        }
    }

    // step 2: per (plane,n2) row: Cc/Cs via 4-fold n3 symmetry + Chebyshev; then P,Q
    if (t < 128) {
        int p = t >> 6, n2 = t & 63;
        const float* row = &sx[p][n2*SPAD];
        float Cc[8], Cs[7];
        float v0 = row[0], v32 = row[32], v16 = row[16], v48 = row[48];
        float ep = v16 + v48, em = v16 - v48;
        float ce = v0 + v32, co = v0 - v32;
        Cc[0] = ce + ep;  Cc[4] = ce + ep;
        Cc[2] = ce - ep;  Cc[6] = ce - ep;
        Cc[1] = co; Cc[3] = co; Cc[5] = co; Cc[7] = co;
        Cs[0] = em;  Cs[2] = -em;  Cs[4] = em;  Cs[6] = -em;   // k = 1,3,5,7
        Cs[1] = 0.f; Cs[3] = 0.f;  Cs[5] = 0.f;                // k = 2,4,6
        #pragma unroll 3
        for (int n3 = 1; n3 < 16; n3++) {
            float vA = row[n3], vB = row[64 - n3];
            float vC = row[32 - n3], vD = row[32 + n3];
            float abp = vA + vB, abm = vA - vB;
            float cdp = vC + vD, dcm = vD - vC;
            float pe = abp + cdp, po = abp - cdp;
            float qe = abm + dcm, qo = abm - dcm;
            float c1 = s_ct[n3], s1 = s_st[n3];
            float tw = c1 + c1;
            float tc[7], ts[7];
            tc[0] = c1; ts[0] = s1;
            tc[1] = fmaf(tw, c1, -1.f);
            ts[1] = tw * s1;
            #pragma unroll
            for (int k = 2; k < 7; k++) {
                tc[k] = fmaf(tw, tc[k-1], -tc[k-2]);
                ts[k] = fmaf(tw, ts[k-1], -ts[k-2]);
            }
            Cc[0] += pe;
            Cc[1] = fmaf(po, tc[0], Cc[1]);
            Cc[2] = fmaf(pe, tc[1], Cc[2]);
            Cc[3] = fmaf(po, tc[2], Cc[3]);
            Cc[4] = fmaf(pe, tc[3], Cc[4]);
            Cc[5] = fmaf(po, tc[4], Cc[5]);
            Cc[6] = fmaf(pe, tc[5], Cc[6]);
            Cc[7] = fmaf(po, tc[6], Cc[7]);
            Cs[0] = fmaf(qo, ts[0], Cs[0]);
            Cs[1] = fmaf(qe, ts[1], Cs[1]);
            Cs[2] = fmaf(qo, ts[2], Cs[2]);
            Cs[3] = fmaf(qe, ts[3], Cs[3]);
            Cs[4] = fmaf(qo, ts[4], Cs[4]);
            Cs[5] = fmaf(qe, ts[5], Cs[5]);
            Cs[6] = fmaf(qo, ts[6], Cs[6]);
        }
        #pragma unroll
        for (int k = 0; k < 8; k++) {
            float cs_ = (k == 0) ? 0.f : Cs[k-1];
            float ck = s_ct[k], sk = s_st[k];
            sP[p][k][n2] = Cc[k] * (1.f - sk) - cs_ * ck;
            sQ[p][k][n2] = Cc[k] * ck - cs_ * (1.f + sk);
        }
    }
    __syncthreads();

    // step 3: per (plane,k2,k3): A = sum c2*P + s2*Q ; B = sum c2*Q - s2*P
    if (t < 128) {
        int pp = t >> 6, k2 = (t >> 3) & 7, k3 = t & 7;
        float A  = sP[pp][k3][0];
        float Bv = sQ[pp][k3][0];
        float sg = (k2 & 1) ? -1.f : 1.f;
        A  = fmaf(sg, sP[pp][k3][32], A);
        Bv = fmaf(sg, sQ[pp][k3][32], Bv);
        #pragma unroll 4
        for (int n2i = 1; n2i < 32; n2i++) {
            int tt = (k2 * n2i) & 63;
            float c = s_ct[tt], s = s_st[tt];
            float Pa = sP[pp][k3][n2i], Pb = sP[pp][k3][64 - n2i];
            float Qa = sQ[pp][k3][n2i], Qb = sQ[pp][k3][64 - n2i];
            A  = fmaf(c, Pa + Pb, fmaf(s, Qa - Qb, A));
            Bv = fmaf(c, Qa + Qb, fmaf(-s, Pa - Pb, Bv));
        }
        int n1 = pp ? n1b : n1a;
        int ob = (((bc << 6) + n1) << 7);
        g_AB[ob + (k2 << 3) + k3]      = A;
        g_AB[ob + 64 + (k2 << 3) + k3] = Bv;
    }

    // reduce s0,c0,c2 over the block
    unsigned m = 0xffffffffu;
    #pragma unroll
    for (int s = 16; s > 0; s >>= 1) {
        s0 += __shfl_down_sync(m, s0, s);
        c0 += __shfl_down_sync(m, c0, s);
        c2 += __shfl_down_sync(m, c2, s);
    }
    int lane = t & 31, wid = t >> 5;
    if (lane == 0) { s_red[0][wid] = s0; s_red[1][wid] = c0; s_red[2][wid] = c2; }
    __syncthreads();
    if (t == 0) {
        float a0 = 0, a1 = 0, a2 = 0;
        #pragma unroll
        for (int w8 = 0; w8 < 8; w8++) { a0 += s_red[0][w8]; a1 += s_red[1][w8]; a2 += s_red[2][w8]; }
        int base = (bc * 32 + pr) * 3;
        g_part[base + 0] = a0;
        g_part[base + 1] = a1;
        g_part[base + 2] = a2;
    }
}

// ---------------- forward stage B: contract n1, finalize norm1, write x1 ----
__global__ void __launch_bounds__(512) k_fwdB() {
    __shared__ float s_ct[64], s_st[64];
    __shared__ float sAB[64*128];
    __shared__ float s_inv;
    int t  = threadIdx.x;
    int bc = blockIdx.x;
    init_tables(s_ct, s_st, t);
    if (t == 64) {
        float s0 = 0, c0 = 0, c2 = 0;
        #pragma unroll 8
        for (int pr = 0; pr < 32; pr++) {
            int base = (bc * 32 + pr) * 3;
            s0 += g_part[base + 0];
            c0 += g_part[base + 1];
            c2 += g_part[base + 2];
        }
        float v = (float)NT * (s0 + 0.5f * (c0 - c2));
        s_inv = (v > 0.f) ? rsqrtf(v) : 0.f;
    }
    {
        const float4* src = (const float4*)(g_AB + ((size_t)bc << 13));
        float4* dst = (float4*)sAB;
        #pragma unroll
        for (int r = 0; r < 4; r++) dst[t + (r << 9)] = src[t + (r << 9)];
    }
    __syncthreads();

    int k1 = t >> 6, kk = t & 63;
    float H = sAB[kk];                               // n1 = 0
    float sg = (k1 & 1) ? -1.f : 1.f;
    H = fmaf(sg, sAB[(32 << 7) + kk], H);            // n1 = 32
    #pragma unroll 4
    for (int n1 = 1; n1 < 32; n1++) {
        int tt = (k1 * n1) & 63;
        float c = s_ct[tt], s = s_st[tt];
        float Aa = sAB[(n1 << 7) + kk],      Ab = sAB[((64 - n1) << 7) + kk];
        float Ba = sAB[(n1 << 7) + 64 + kk], Bb = sAB[((64 - n1) << 7) + 64 + kk];
        H = fmaf(c, Aa + Ab, fmaf(s, Ba - Bb, H));
    }
    g_x1[bc * 512 + t] = H * s_inv;
}

// ---------------- conv partial: grid (4 ig, 128 bo), 512 thr ----------------
__global__ void __launch_bounds__(512) k_convp() {
    int ig = blockIdx.x;            // 0..3 (i-group of 8)
    int bo = blockIdx.y;            // 0..127
    int b = bo >> 5, o = bo & 31;
    int k = threadIdx.x;
    int k1 = k >> 6, k2 = (k >> 3) & 7, k3 = k & 7;
    int nk = (((8-k1)&7) << 6) | (((8-k2)&7) << 3) | ((8-k3)&7);
    float acc = 0.f;
    #pragma unroll
    for (int ii = 0; ii < 8; ii++) {
        int i = (ig << 3) + ii;
        const float* xA = g_x1 + ((b * 32 + i) << 9);
        int wb = (i * 32 + o) << 9;
        acc = fmaf(xA[k],  g_wp[wb + k], acc);
        acc = fmaf(xA[nk], g_wm[wb + k], acc);
    }
    g_yp[(((ig << 7) | bo) << 9) + k] = acc;
}

// ---------------- I1+I2+I3 fused (+ y assembly + norm2) ----------------
__global__ void __launch_bounds__(256, 2) k_i23(float* __restrict__ out) {
    __shared__ float s_ct[64], s_st[64];
    __shared__ float s_y[512];
    __shared__ float s_tc[4096], s_ts[4096];
    __shared__ float sa[256];
    __shared__ float s_sc;
    int t = threadIdx.x;
    int tile = blockIdx.x;   // 0..3
    int bo   = blockIdx.y;   // 0..127

    init_tables(s_ct, s_st, t);

    float y0 = 0.f, y1 = 0.f;
    #pragma unroll
    for (int ig = 0; ig < 4; ig++) {
        const float* yp = g_yp + (((ig << 7) | bo) << 9);
        y0 += yp[t];
        y1 += yp[t + 256];
    }
    sa[t] = ((t == 0) ? 1.5f : 1.0f) * y0 * y0 + y1 * y1;
    __syncthreads();
    for (int s = 128; s > 0; s >>= 1) {
        if (t < s) sa[t] += sa[t + s];
        __syncthreads();
    }
    if (t == 0) {
        float v = sa[0];
        s_sc = (v > 0.f) ? rsqrtf((float)NT * v) / (float)NT : 0.f;
    }
    __syncthreads();
    s_y[t]       = y0 * s_sc;
    s_y[t + 256] = y1 * s_sc;
    __syncthreads();

    int j3 = t & 63;
    int jg = t >> 6;

    // stage I1
    {
        float U[8], V[8];
        #pragma unroll
        for (int k3 = 0; k3 < 8; k3++) {
            int t0 = (j3 * k3) & 63;
            int t1 = (j3 * (k3 + 1)) & 63;
            U[k3] = s_ct[t0] - s_st[t1];
            V[k3] = s_ct[t1] - s_st[t0];
        }
        #pragma unroll
        for (int r = 0; r < 16; r++) {
            int kk = jg + 4 * r;
            float a = 0.f, bsum = 0.f;
            #pragma unroll
            for (int k3 = 0; k3 < 8; k3++) {
                float yv = s_y[(kk << 3) + k3];
                a    = fmaf(yv, U[k3], a);
                bsum = fmaf(yv, V[k3], bsum);
            }
            s_tc[(kk << 6) + j3] = a;
            s_ts[(kk << 6) + j3] = bsum;
        }
    }
    __syncthreads();

    float* ob = out + ((size_t)bo << 18);

    // stage I2 for all 4 j2 values; LDS hoisted out of the v loop
    float p[4][8], q[4][8];
    int j2v[4];
    #pragma unroll
    for (int v = 0; v < 4; v++) {
        j2v[v] = tile * 16 + jg * 4 + v;
        #pragma unroll
        for (int k1 = 0; k1 < 8; k1++) { p[v][k1] = 0.f; q[v][k1] = 0.f; }
    }
    #pragma unroll
    for (int k2 = 0; k2 < 8; k2++) {
        float cv[4], sv[4];
        #pragma unroll
        for (int v = 0; v < 4; v++) {
            int tt = (j2v[v] * k2) & 63;
            cv[v] = s_ct[tt];
            sv[v] = s_st[tt];
        }
        #pragma unroll
        for (int k1 = 0; k1 < 8; k1++) {
            float a  = s_tc[((k1 * 8 + k2) << 6) + j3];
            float bb = s_ts[((k1 * 8 + k2) << 6) + j3];
            #pragma unroll
            for (int v = 0; v < 4; v++) {
                p[v][k1] = fmaf(a, cv[v], fmaf(bb,  sv[v], p[v][k1]));
                q[v][k1] = fmaf(bb, cv[v], fmaf(-a, sv[v], q[v][k1]));
            }
        }
    }

    // stage I3: j1 outer (trig hoisted), 4-fold symmetry over j1
    #pragma unroll 1
    for (int j1 = 0; j1 <= 16; j1++) {
        float tcv[7], tsv[7];
        #pragma unroll
        for (int k = 1; k < 8; k++) {
            int tt = (j1 * k) & 63;
            tcv[k-1] = s_ct[tt];
            tsv[k-1] = s_st[tt];
        }
        int o0 = j1 << 12;
        int o1 = ((64 - j1) & 63) << 12;
        int o2 = ((j1 + 32) & 63) << 12;
        int o3 = ((32 - j1) & 63) << 12;
        #pragma unroll
        for (int v = 0; v < 4; v++) {
            float pce = p[v][0], pco = 0.f, qse = 0.f, qso = 0.f;
            #pragma unroll
            for (int k = 1; k < 8; k++) {
                if (k & 1) { pco = fmaf(p[v][k], tcv[k-1], pco); qso = fmaf(q[v][k], tsv[k-1], qso); }
                else       { pce = fmaf(p[v][k], tcv[k-1], pce); qse = fmaf(q[v][k], tsv[k-1], qse); }
            }
            float A = pce + pco, Bv = qse + qso;
            float C = pce - pco, D  = qse - qso;
            float* op = ob + (j2v[v] << 6) + j3;
            op[o0] = A + Bv;
            op[o1] = A - Bv;
            op[o2] = C + D;
            op[o3] = C - D;
        }
    }
}

extern "C" void kernel_launch(void* const* d_in, const int* in_sizes, int n_in,
                              void* d_out, int out_size) {
    const float* x = (const float*)d_in[0];       // (4,32,64,64,64)
    const float* w = (const float*)d_in[1];       // (32,32,8,8,8)
    float* out = (float*)d_out;                   // (4,32,64,64,64)

    k_fwdA<<<dim3(33, NCH), 256>>>(x, w);
    k_fwdB<<<NCH, 512>>>();
    k_convp<<<dim3(4, NCH), 512>>>();
    k_i23<<<dim3(4, NCH), 256>>>(out);
}